// round 8
// baseline (speedup 1.0000x reference)
#include <cuda_runtime.h>

#define Bb 4
#define Tt 512
#define Cc 128
#define NROWS (Bb * Tt)  // 2048
#define NEG_INF (-1e22f)
#define TI 8

// Q stored transposed: qT[d][global_row]; K row-major.
__device__ float g_qT[Cc * NROWS];
__device__ float g_k[NROWS * Cc];

typedef unsigned long long u64;

// ---- packed f32x2 helpers -------------------------------------------------
__device__ __forceinline__ u64 add2(u64 a, u64 b) {
    u64 s;
    asm("add.rn.f32x2 %0, %1, %2;" : "=l"(s) : "l"(a), "l"(b));
    return s;
}
__device__ __forceinline__ u64 relu2(u64 s) {
    asm("{\n\t"
        ".reg .f32 lo, hi;\n\t"
        "mov.b64 {lo, hi}, %0;\n\t"
        "max.f32 lo, lo, 0f00000000;\n\t"
        "max.f32 hi, hi, 0f00000000;\n\t"
        "mov.b64 %0, {lo, hi};\n\t"
        "}"
        : "+l"(s));
    return s;
}
__device__ __forceinline__ void fma2(u64& acc, u64 a, u64 b) {
    asm("fma.rn.f32x2 %0, %1, %2, %0;" : "+l"(acc) : "l"(a), "l"(b));
}
__device__ __forceinline__ u64 dup2(float w) {
    u64 r;
    asm("mov.b64 %0, {%1, %1};" : "=l"(r) : "f"(w));
    return r;
}
__device__ __forceinline__ u64 pack2(float lo, float hi) {
    u64 r;
    asm("mov.b64 %0, {%1, %2};" : "=l"(r) : "f"(lo), "f"(hi));
    return r;
}
__device__ __forceinline__ float lo2(u64 a) { return __uint_as_float((unsigned)a); }
__device__ __forceinline__ float hi2(u64 a) { return __uint_as_float((unsigned)(a >> 32)); }

// ---------------------------------------------------------------------------
// Kernel 1: projection, f32x2 packed over row pairs.
// Grid (NROWS/16 = 128, 1, 2): z=0 Q (transposed out), z=1 K (row-major out).
// Block 512 threads: col = tid&127, rowgroup rg = tid>>7 (4 rows each).
// smem: xp[d][rp] u64, rp = row pair 0..7  (8KB)
// ---------------------------------------------------------------------------
#define PJ_SMEM_BYTES (1024 * 8)

__global__ void __launch_bounds__(512) proj_kernel(const float* __restrict__ x,
                                                   const float* __restrict__ WQ,
                                                   const float* __restrict__ WK) {
    extern __shared__ u64 xp[];  // [128 d][8 rp]

    const int tid  = threadIdx.x;
    const int row0 = blockIdx.x * 16;
    const float* W = blockIdx.z ? WK : WQ;

    // stage x as packed row pairs: xp[d*8+rp] = (x[row0+2rp][d], x[row0+2rp+1][d])
#pragma unroll
    for (int t = 0; t < 2; t++) {
        int idx = tid + 512 * t;  // 0..1023
        int d = idx >> 3, rp = idx & 7;
        float lo = x[(size_t)(row0 + 2 * rp) * Cc + d];
        float hi = x[(size_t)(row0 + 2 * rp + 1) * Cc + d];
        xp[d * 8 + rp] = pack2(lo, hi);
    }
    __syncthreads();

    const int col = tid & 127;
    const int rg  = tid >> 7;  // 0..3 -> rows 4rg..4rg+3 (pairs 2rg, 2rg+1)

    u64 a0 = 0, a1 = 0;
#pragma unroll 8
    for (int d2 = 0; d2 < 64; d2++) {
        int d = 2 * d2;
        u64 wd0 = dup2(W[(size_t)d * Cc + col]);
        u64 wd1 = dup2(W[(size_t)(d + 1) * Cc + col]);
        ulonglong2 x0 = *(const ulonglong2*)(xp + d * 8 + 2 * rg);
        ulonglong2 x1 = *(const ulonglong2*)(xp + (d + 1) * 8 + 2 * rg);
        fma2(a0, wd0, x0.x);
        fma2(a1, wd0, x0.y);
        fma2(a0, wd1, x1.x);
        fma2(a1, wd1, x1.y);
    }

    if (blockIdx.z) {
        g_k[(size_t)(row0 + 4 * rg + 0) * Cc + col] = lo2(a0);
        g_k[(size_t)(row0 + 4 * rg + 1) * Cc + col] = hi2(a0);
        g_k[(size_t)(row0 + 4 * rg + 2) * Cc + col] = lo2(a1);
        g_k[(size_t)(row0 + 4 * rg + 3) * Cc + col] = hi2(a1);
    } else {
        float4 v = make_float4(lo2(a0), hi2(a0), lo2(a1), hi2(a1));
        *(float4*)(g_qT + (size_t)col * NROWS + row0 + 4 * rg) = v;
    }
}

// ---------------------------------------------------------------------------
// Kernel 2: fused score + masked softmax + AV. Grid (64, 4), 512 threads.
// Thread j = tid covers ALL 8 i rows (packed as 4 i-pair u64 accs).
// smem (u64 units): kid [0,512) | psd [512,640) | sc(float) [640,1664)
//                   scd [1664,6784)  scd[j][10] — EVEN stride, 16B-aligned
//                   (sc reused as AV reduce buf)
// ---------------------------------------------------------------------------
#define SCD_STRIDE 10
#define AT_SMEM_U64 (1664 + Tt * SCD_STRIDE)
#define AT_SMEM_BYTES (AT_SMEM_U64 * 8)

__global__ void __launch_bounds__(512, 2) attn_kernel(const float* __restrict__ x,
                                                      const float* __restrict__ adj,
                                                      const float* __restrict__ p,
                                                      float* __restrict__ out) {
    extern __shared__ u64 asm_u[];
    u64*   kid = asm_u;                   // [4 m][128 d]: (k[2m][d], k[2m+1][d])
    u64*   psd = asm_u + 512;             // [128] p dup'd
    float* sc  = (float*)(asm_u + 640);   // [8][512] raw scores (reused as AV buf)
    u64*   scd = asm_u + 1664;            // [512 j][10] dup'd weights

    const int tid = threadIdx.x;
    const int b   = blockIdx.y;
    const int i0  = blockIdx.x * TI;

    // stage k as i-pairs + p dup'd
    {
        int m = tid >> 7, d = tid & 127;
        float lo = g_k[(size_t)(b * Tt + i0 + 2 * m) * Cc + d];
        float hi = g_k[(size_t)(b * Tt + i0 + 2 * m + 1) * Cc + d];
        kid[m * 128 + d] = pack2(lo, hi);
    }
    if (tid < 128) psd[tid] = dup2(p[tid]);
    __syncthreads();

    // ================= score: thread = 1 j x 8 i (4 packed pairs) ==========
    {
        const int    j  = tid;
        const float* qb = g_qT + b * Tt + j;

        u64 a0 = 0, a1 = 0, a2 = 0, a3 = 0;

#pragma unroll 4
        for (int d2 = 0; d2 < 64; d2++) {
            int d   = 2 * d2;
            u64 qd0 = dup2(qb[(size_t)d * NROWS]);
            u64 qd1 = dup2(qb[(size_t)(d + 1) * NROWS]);
            ulonglong2 pp = *(const ulonglong2*)(psd + d);
            ulonglong2 k0 = *(const ulonglong2*)(kid + 0 * 128 + d);
            ulonglong2 k1 = *(const ulonglong2*)(kid + 1 * 128 + d);
            ulonglong2 k2 = *(const ulonglong2*)(kid + 2 * 128 + d);
            ulonglong2 k3 = *(const ulonglong2*)(kid + 3 * 128 + d);

            fma2(a0, pp.x, relu2(add2(qd0, k0.x)));
            fma2(a1, pp.x, relu2(add2(qd0, k1.x)));
            fma2(a2, pp.x, relu2(add2(qd0, k2.x)));
            fma2(a3, pp.x, relu2(add2(qd0, k3.x)));
            fma2(a0, pp.y, relu2(add2(qd1, k0.y)));
            fma2(a1, pp.y, relu2(add2(qd1, k1.y)));
            fma2(a2, pp.y, relu2(add2(qd1, k2.y)));
            fma2(a3, pp.y, relu2(add2(qd1, k3.y)));
        }
        sc[0 * Tt + j] = lo2(a0);
        sc[1 * Tt + j] = hi2(a0);
        sc[2 * Tt + j] = lo2(a1);
        sc[3 * Tt + j] = hi2(a1);
        sc[4 * Tt + j] = lo2(a2);
        sc[5 * Tt + j] = hi2(a2);
        sc[6 * Tt + j] = lo2(a3);
        sc[7 * Tt + j] = hi2(a3);
    }
    __syncthreads();

    // ================= masked softmax (warps 0-7, one row each) =============
    const int warp = tid >> 5, lane = tid & 31;
    if (warp < 8) {
        const int    r    = warp;
        const float* arow = adj + ((size_t)(b * Tt) + i0 + r) * Tt;
        float v[16];
        float m = -3.4e38f;
#pragma unroll
        for (int t = 0; t < 16; t++) {
            int   j = lane + 32 * t;
            float s = sc[r * Tt + j];
            s    = (arow[j] > 0.f) ? s : NEG_INF;
            v[t] = s;
            m    = fmaxf(m, s);
        }
#pragma unroll
        for (int o = 16; o; o >>= 1) m = fmaxf(m, __shfl_xor_sync(0xffffffff, m, o));
        float sum = 0.f;
#pragma unroll
        for (int t = 0; t < 16; t++) {
            v[t] = __expf(v[t] - m);
            sum += v[t];
        }
#pragma unroll
        for (int o = 16; o; o >>= 1) sum += __shfl_xor_sync(0xffffffff, sum, o);
        float inv = 1.f / sum;
#pragma unroll
        for (int t = 0; t < 16; t++)
            scd[(lane + 32 * t) * SCD_STRIDE + r] = dup2(v[t] * inv);
    }
    __syncthreads();

    // ================= AV: warp = (ipair m, d-half, j-half) =================
    const int m  = warp & 3;         // i rows 2m, 2m+1
    const int dh = (warp >> 2) & 1;  // d half
    const int jh = warp >> 3;        // j half
    const int d0 = dh * 64 + 2 * lane;

    u64 av0 = 0, av1 = 0;
    const float* xb = x + (size_t)(b * Tt) * Cc + d0;

#pragma unroll 4
    for (int jj = 0; jj < 256; jj++) {
        int        j  = jh * 256 + jj;
        ulonglong2 wp = *(const ulonglong2*)(scd + j * SCD_STRIDE + 2 * m);
        u64        xv = *(const u64*)(xb + (size_t)j * Cc);
        fma2(av0, wp.x, xv);
        fma2(av1, wp.y, xv);
    }
    __syncthreads();

    // reduce j-halves through smem (reuse sc region: 8 warps x 2 x 32 u64 = 4KB)
    u64* buf = (u64*)sc;
    if (jh == 1) {
        buf[(warp - 8) * 64 + lane]      = av0;
        buf[(warp - 8) * 64 + 32 + lane] = av1;
    }
    __syncthreads();
    if (jh == 0) {
        av0 = add2(av0, buf[warp * 64 + lane]);
        av1 = add2(av1, buf[warp * 64 + 32 + lane]);
        *(u64*)(out + (size_t)(b * Tt + i0 + 2 * m + 0) * Cc + d0) = av0;
        *(u64*)(out + (size_t)(b * Tt + i0 + 2 * m + 1) * Cc + d0) = av1;
    }
}

// ---------------------------------------------------------------------------
extern "C" void kernel_launch(void* const* d_in, const int* in_sizes, int n_in,
                              void* d_out, int out_size) {
    const float* x   = (const float*)d_in[0];
    const float* adj = (const float*)d_in[1];
    const float* WQ  = (const float*)d_in[2];
    const float* WK  = (const float*)d_in[3];
    const float* p   = (const float*)d_in[4];
    float*       out = (float*)d_out;

    proj_kernel<<<dim3(NROWS / 16, 1, 2), 512, PJ_SMEM_BYTES>>>(x, WQ, WK);

    cudaFuncSetAttribute(attn_kernel, cudaFuncAttributeMaxDynamicSharedMemorySize,
                         AT_SMEM_BYTES);
    attn_kernel<<<dim3(Tt / TI, Bb), 512, AT_SMEM_BYTES>>>(x, adj, p, out);
}

// round 9
// speedup vs baseline: 1.0907x; 1.0907x over previous
#include <cuda_runtime.h>

#define Bb 4
#define Tt 512
#define Cc 128
#define NROWS (Bb * Tt)  // 2048
#define NEG_INF (-1e22f)
#define TI 8

// Q stored transposed: qT[d][global_row]; K row-major.
__device__ float g_qT[Cc * NROWS];
__device__ float g_k[NROWS * Cc];

typedef unsigned long long u64;

// ---- packed f32x2 helpers -------------------------------------------------
__device__ __forceinline__ u64 add2(u64 a, u64 b) {
    u64 s;
    asm("add.rn.f32x2 %0, %1, %2;" : "=l"(s) : "l"(a), "l"(b));
    return s;
}
__device__ __forceinline__ u64 relu2(u64 s) {
    asm("{\n\t"
        ".reg .f32 lo, hi;\n\t"
        "mov.b64 {lo, hi}, %0;\n\t"
        "max.f32 lo, lo, 0f00000000;\n\t"
        "max.f32 hi, hi, 0f00000000;\n\t"
        "mov.b64 %0, {lo, hi};\n\t"
        "}"
        : "+l"(s));
    return s;
}
__device__ __forceinline__ void fma2(u64& acc, u64 a, u64 b) {
    asm("fma.rn.f32x2 %0, %1, %2, %0;" : "+l"(acc) : "l"(a), "l"(b));
}
__device__ __forceinline__ u64 dup2(float w) {
    u64 r;
    asm("mov.b64 %0, {%1, %1};" : "=l"(r) : "f"(w));
    return r;
}
__device__ __forceinline__ u64 pack2(float lo, float hi) {
    u64 r;
    asm("mov.b64 %0, {%1, %2};" : "=l"(r) : "f"(lo), "f"(hi));
    return r;
}
__device__ __forceinline__ float lo2(u64 a) { return __uint_as_float((unsigned)a); }
__device__ __forceinline__ float hi2(u64 a) { return __uint_as_float((unsigned)(a >> 32)); }

// ---------------------------------------------------------------------------
// Kernel 1: Q/K projection (R4 structure). Grid (64, 2): y=0 Q (transposed
// store), y=1 K (row-major). Block = 32 rows x 128 cols; 256 threads:
// threads 0..127 cols for row-half 0... (thread = 1 col x 32 rows via 2 halves)
// ---------------------------------------------------------------------------
__global__ void __launch_bounds__(256) qk_kernel(const float* __restrict__ x,
                                                 const float* __restrict__ WQ,
                                                 const float* __restrict__ WK) {
    __shared__ float4 xs[32 * 32];  // 32 rows x 128 floats
    const int tid  = threadIdx.x;
    const int row0 = blockIdx.x * 32;
    const float* W = blockIdx.y ? WK : WQ;

    // cooperative coalesced load of the 32-row x tile
#pragma unroll
    for (int t = 0; t < 4; t++) {
        int f4 = tid + 256 * t;  // 0..1023
        int r  = f4 >> 5, c = f4 & 31;
        xs[f4] = ((const float4*)(x + (size_t)(row0 + r) * Cc))[c];
    }
    __syncthreads();

    const int col = tid & 127;
    const int rh  = tid >> 7;  // 0/1 -> rows rh*16 .. rh*16+15

    float acc[16];
#pragma unroll
    for (int r = 0; r < 16; r++) acc[r] = 0.f;

#pragma unroll 4
    for (int d4 = 0; d4 < 32; d4++) {
        float w0 = W[(4 * d4 + 0) * Cc + col];
        float w1 = W[(4 * d4 + 1) * Cc + col];
        float w2 = W[(4 * d4 + 2) * Cc + col];
        float w3 = W[(4 * d4 + 3) * Cc + col];
#pragma unroll
        for (int r = 0; r < 16; r++) {
            float4 xv = xs[(rh * 16 + r) * 32 + d4];
            acc[r] += xv.x * w0;
            acc[r] += xv.y * w1;
            acc[r] += xv.z * w2;
            acc[r] += xv.w * w3;
        }
    }

    if (blockIdx.y) {
        // K row-major
#pragma unroll
        for (int r = 0; r < 16; r++)
            g_k[(size_t)(row0 + rh * 16 + r) * Cc + col] = acc[r];
    } else {
        // Q transposed: qT[col][row0 + rh*16 + r], float4 over rows
        float* qb = g_qT + (size_t)col * NROWS + row0 + rh * 16;
#pragma unroll
        for (int r4 = 0; r4 < 4; r4++) {
            float4 v = make_float4(acc[4 * r4 + 0], acc[4 * r4 + 1],
                                   acc[4 * r4 + 2], acc[4 * r4 + 3]);
            *(float4*)(qb + 4 * r4) = v;
        }
    }
}

// ---------------------------------------------------------------------------
// Kernel 2 (R6 verbatim): fused score + masked softmax + AV.
// Grid (64, 4), 512 threads.
// smem (u64): ksd [0,1024) | psd [1024,1152) | sc(float) [1152,3200)
//             scd [3200,7296)  (scd reused as AV reduction buffer)
// ---------------------------------------------------------------------------
#define AT_SMEM_U64 7296
#define AT_SMEM_BYTES (AT_SMEM_U64 * 8)

__global__ void __launch_bounds__(512, 2) attn_kernel(const float* __restrict__ x,
                                                      const float* __restrict__ adj,
                                                      const float* __restrict__ p,
                                                      float* __restrict__ out) {
    extern __shared__ u64 asm_u[];
    u64*   ksd = asm_u;                   // [8][128] k duplicated
    u64*   psd = asm_u + 1024;            // [128]    p duplicated
    float* sc  = (float*)(asm_u + 1152);  // [8][512] raw scores
    u64*   scd = asm_u + 3200;            // [8][512] softmax weights dup'd

    const int tid = threadIdx.x;
    const int b   = blockIdx.y;
    const int i0  = blockIdx.x * TI;

    // stage k rows (dup'd) + p (dup'd)
#pragma unroll
    for (int t = 0; t < 2; t++) {
        int idx = tid + 512 * t;  // 0..1023
        int r = idx >> 7, d = idx & 127;
        ksd[r * 128 + d] = dup2(g_k[(size_t)(b * Tt + i0 + r) * Cc + d]);
    }
    if (tid < 128) psd[tid] = dup2(p[tid]);
    __syncthreads();

    // ================= score phase: thread = 2i x 4j, packed over j =========
    {
        const int ig = tid >> 7;         // 0..3 -> rows 2ig, 2ig+1
        const int j0 = (tid & 127) * 4;  // 4 consecutive j's
        const float* qb = g_qT + b * Tt + j0;

        u64 a00 = 0, a01 = 0, a10 = 0, a11 = 0;
        const u64* k0p = ksd + (2 * ig + 0) * 128;
        const u64* k1p = ksd + (2 * ig + 1) * 128;

#pragma unroll 4
        for (int d4 = 0; d4 < 32; d4++) {
#pragma unroll
            for (int e = 0; e < 4; e++) {
                int d = 4 * d4 + e;
                ulonglong2 q = *(const ulonglong2*)(qb + (size_t)d * NROWS);
                u64 pd = psd[d];
                u64 k0 = k0p[d];
                u64 k1 = k1p[d];
                fma2(a00, pd, relu2(add2(q.x, k0)));
                fma2(a01, pd, relu2(add2(q.y, k0)));
                fma2(a10, pd, relu2(add2(q.x, k1)));
                fma2(a11, pd, relu2(add2(q.y, k1)));
            }
        }
        u64* s0 = (u64*)(sc + (2 * ig + 0) * Tt + j0);
        u64* s1 = (u64*)(sc + (2 * ig + 1) * Tt + j0);
        s0[0] = a00; s0[1] = a01;
        s1[0] = a10; s1[1] = a11;
    }
    __syncthreads();

    // ================= masked softmax (warps 0-7, one row each) =============
    const int warp = tid >> 5, lane = tid & 31;
    if (warp < 8) {
        const int    r    = warp;
        const float* arow = adj + ((size_t)(b * Tt) + i0 + r) * Tt;
        float v[16];
        float m = -3.4e38f;
#pragma unroll
        for (int t = 0; t < 16; t++) {
            int   j = lane + 32 * t;
            float s = sc[r * Tt + j];
            s    = (arow[j] > 0.f) ? s : NEG_INF;
            v[t] = s;
            m    = fmaxf(m, s);
        }
#pragma unroll
        for (int o = 16; o; o >>= 1) m = fmaxf(m, __shfl_xor_sync(0xffffffff, m, o));
        float sum = 0.f;
#pragma unroll
        for (int t = 0; t < 16; t++) {
            v[t] = __expf(v[t] - m);
            sum += v[t];
        }
#pragma unroll
        for (int o = 16; o; o >>= 1) sum += __shfl_xor_sync(0xffffffff, sum, o);
        float inv = 1.f / sum;
#pragma unroll
        for (int t = 0; t < 16; t++)
            scd[r * Tt + lane + 32 * t] = dup2(v[t] * inv);
    }
    __syncthreads();

    // ================= AV: warps = 8 jq x 2 dq; thread = 8i x 2d ===========
    const int jq = warp >> 1;  // 0..7 -> 64 j's
    const int dq = warp & 1;   // 0/1 -> d half
    const int d0 = dq * 64 + 2 * lane;

    u64 av[8];
#pragma unroll
    for (int i = 0; i < 8; i++) av[i] = 0ull;

    const float* xb = x + (size_t)(b * Tt) * Cc;
#pragma unroll 4
    for (int jj = 0; jj < 64; jj++) {
        int j  = jq * 64 + jj;
        u64 xv = *(const u64*)(xb + (size_t)j * Cc + d0);
#pragma unroll
        for (int i = 0; i < 8; i++) fma2(av[i], scd[i * Tt + j], xv);
    }
    __syncthreads();

    // reduce over jq through smem (reuse scd region)
    u64* buf = scd;  // 7 * 8 * 64 u64 = 28KB
    if (jq != 0) {
#pragma unroll
        for (int i = 0; i < 8; i++)
            buf[((jq - 1) * 8 + i) * 64 + dq * 32 + lane] = av[i];
    }
    __syncthreads();
    if (jq == 0) {
#pragma unroll
        for (int q = 0; q < 7; q++)
#pragma unroll
            for (int i = 0; i < 8; i++)
                av[i] = add2(av[i], buf[(q * 8 + i) * 64 + dq * 32 + lane]);
#pragma unroll
        for (int i = 0; i < 8; i++)
            *(u64*)(out + (size_t)(b * Tt + i0 + i) * Cc + d0) = av[i];
    }
}

// ---------------------------------------------------------------------------
extern "C" void kernel_launch(void* const* d_in, const int* in_sizes, int n_in,
                              void* d_out, int out_size) {
    const float* x   = (const float*)d_in[0];
    const float* adj = (const float*)d_in[1];
    const float* WQ  = (const float*)d_in[2];
    const float* WK  = (const float*)d_in[3];
    const float* p   = (const float*)d_in[4];
    float*       out = (float*)d_out;

    qk_kernel<<<dim3(NROWS / 32, 2), 256>>>(x, WQ, WK);

    cudaFuncSetAttribute(attn_kernel, cudaFuncAttributeMaxDynamicSharedMemorySize,
                         AT_SMEM_BYTES);
    attn_kernel<<<dim3(Tt / TI, Bb), 512, AT_SMEM_BYTES>>>(x, adj, p, out);
}